// round 4
// baseline (speedup 1.0000x reference)
#include <cuda_runtime.h>
#include <cuda_fp16.h>
#include <cstdint>

#define NTOK   65536
#define DIMC   256
#define NCODE  1024
#define HWSZ   4096
#define ZSZ    16777216
#define OFF_ZQ      1
#define OFF_PERP    16777217
#define OFF_MINENC  16777218ULL
#define OFF_IDX     83886082ULL

#define TOKT   64           // tokens per block
#define SA     260          // A32 row stride (floats); 260*4=1040, 16B aligned
#define MARGIN 1e-2f
#define NSLOT  4

// smem byte offsets
#define O_A32   0           // 64*260*4 = 66560
#define O_AH    66560       // 32*64*4  = 8192   (half2 [k2][tok])
#define O_BS    74752       // 32*128*4 = 16384  (half2 [k2][code])
#define O_EN    91136       // 1024*4   = 4096
#define O_BEST  95232       // 64*4
#define O_CNT   95488       // 64*4
#define O_CAND  95744       // 64*16*4 = 4096
#define SMEM_BYTES 99840

// ---------------- scratch ----------------
__device__ float   g_et[DIMC * NCODE];     // [c][k] for k_epi gather
__device__ __half2 g_eh2[128 * NCODE];     // [c2][k] half2 codes (dims 2c2,2c2+1)
__device__ float   g_en[NCODE];
__device__ int     g_idx[NTOK];
__device__ int     g_hist[NCODE];
__device__ double  g_loss;

__device__ __forceinline__ unsigned fenc(float f) {
    unsigned u = __float_as_uint(f);
    return (u & 0x80000000u) ? ~u : (u | 0x80000000u);
}
__device__ __forceinline__ float fdec(unsigned e) {
    unsigned u = (e & 0x80000000u) ? (e & 0x7FFFFFFFu) : ~e;
    return __uint_as_float(u);
}

// ---------------- pass1: HFMA2 screen + exact fp32 re-rank ----------------
__global__ void __launch_bounds__(256, 2) k_pass1(const float* __restrict__ z,
                                                  const float* __restrict__ embed) {
    extern __shared__ char sm[];
    float*    A32   = (float*)(sm + O_A32);
    __half2*  AH    = (__half2*)(sm + O_AH);
    __half2*  BS    = (__half2*)(sm + O_BS);
    float*    EN    = (float*)(sm + O_EN);
    unsigned* sbest = (unsigned*)(sm + O_BEST);
    int*      scnt  = (int*)(sm + O_CNT);
    int*      scand = (int*)(sm + O_CAND);

    int tid = threadIdx.x;
    int tx  = tid & 15;            // code group: codes tx*8..+7 within 128-tile
    int ty  = tid >> 4;            // token group: tokens ty*4..+3
    int n0  = blockIdx.x * TOKT;
    int b   = n0 >> 12, hw0 = n0 & 4095;

    if (tid < 64) { sbest[tid] = 0xFFFFFFFFu; scnt[tid] = 0; }
    for (int i = tid; i < NCODE; i += 256) EN[i] = g_en[i];

    // ---- load exact A32[tok][dim] (coalesced float4 over hw) ----
    {
        const float4* zb = (const float4*)z + ((size_t)b * 256) * 1024 + (hw0 >> 2);
#pragma unroll
        for (int j = 0; j < 16; j++) {
            int u  = tid + j * 256;       // 4096 float4
            int c  = u >> 4, t4 = u & 15;
            float4 v = zb[(size_t)c * 1024 + t4];
            A32[(t4 * 4 + 0) * SA + c] = v.x;
            A32[(t4 * 4 + 1) * SA + c] = v.y;
            A32[(t4 * 4 + 2) * SA + c] = v.z;
            A32[(t4 * 4 + 3) * SA + c] = v.w;
        }
    }

    // ---- candidate state ----
    float bv[4] = {3.4e38f, 3.4e38f, 3.4e38f, 3.4e38f};
    float sd[4][NSLOT];
    int   sc[4][NSLOT];
    int   cnt[4] = {0, 0, 0, 0};
    int   ovf = 0;

    float accf[4][8];
#pragma unroll
    for (int i = 0; i < 4; i++)
#pragma unroll
        for (int j = 0; j < 8; j++) accf[i][j] = 0.0f;

    // prefetch B chunk (ct=0,kc=0): 1024 float4
    float4 rv[4];
    {
        const float4* src = (const float4*)g_eh2;   // row = 256 float4
#pragma unroll
        for (int j = 0; j < 4; j++) {
            int u = tid + j * 256;
            int k2 = u >> 5, c4 = u & 31;
            rv[j] = src[(size_t)k2 * 256 + c4];
        }
    }

    for (int ct = 0; ct < 8; ct++) {
        for (int kc = 0; kc < 4; kc++) {
            __syncthreads();      // previous compute done reading BS/AH
            // store prefetched B chunk
            {
                float4* bd = (float4*)BS;
#pragma unroll
                for (int j = 0; j < 4; j++) {
                    int u = tid + j * 256;
                    int k2 = u >> 5, c4 = u & 31;
                    bd[k2 * 32 + c4] = rv[j];
                }
            }
            // convert A chunk kc: AH[k2][tok] = half2(A32[tok][kc*64+2k2], +1)
            {
#pragma unroll
                for (int j = 0; j < 8; j++) {
                    int v = tid + j * 256;       // 2048 entries
                    int tok = v & 63, k2 = v >> 6;
                    const float* ap = A32 + tok * SA + kc * 64 + 2 * k2;
                    AH[k2 * 64 + tok] = __floats2half2_rn(ap[0], ap[1]);
                }
            }
            __syncthreads();

            // prefetch next B chunk
            int q = ct * 4 + kc;
            if (q < 31) {
                int nct = (q + 1) >> 2, nkc = (q + 1) & 3;
                const float4* src = (const float4*)g_eh2 + (size_t)(nkc * 32) * 256 + nct * 32;
#pragma unroll
                for (int j = 0; j < 4; j++) {
                    int u = tid + j * 256;
                    int k2 = u >> 5, c4 = u & 31;
                    rv[j] = src[(size_t)k2 * 256 + c4];
                }
            }

            // ---- compute: 32 k2-steps, 32 HFMA2 each ----
            __half2 acc2[4][8];
#pragma unroll
            for (int i = 0; i < 4; i++)
#pragma unroll
                for (int j = 0; j < 8; j++) acc2[i][j] = __floats2half2_rn(0.f, 0.f);

#pragma unroll 4
            for (int k2 = 0; k2 < 32; k2++) {
                __half2 a2[4], b2[8];
                *(float4*)a2       = *(const float4*)&AH[k2 * 64 + ty * 4];
                *(float4*)b2       = *(const float4*)&BS[k2 * 128 + tx * 8];
                *(float4*)(b2 + 4) = *(const float4*)&BS[k2 * 128 + tx * 8 + 4];
#pragma unroll
                for (int i = 0; i < 4; i++)
#pragma unroll
                    for (int j = 0; j < 8; j++)
                        acc2[i][j] = __hfma2(a2[i], b2[j], acc2[i][j]);
            }
            // fold to fp32
#pragma unroll
            for (int i = 0; i < 4; i++)
#pragma unroll
                for (int j = 0; j < 8; j++) {
                    float2 f = __half22float2(acc2[i][j]);
                    accf[i][j] += f.x + f.y;
                }
        }

        // ---- epilogue for code tile ct ----
#pragma unroll
        for (int j = 0; j < 8; j++) {
            int code = ct * 128 + tx * 8 + j;
            float enj = EN[code];
#pragma unroll
            for (int i = 0; i < 4; i++) {
                float dp = enj - 2.0f * accf[i][j];
                if (dp < bv[i] + MARGIN) {
                    if (cnt[i] == NSLOT) {
                        int m = 0;
                        for (int qq = 0; qq < NSLOT; qq++)
                            if (sd[i][qq] < bv[i] + MARGIN) {
                                sd[i][m] = sd[i][qq]; sc[i][m] = sc[i][qq]; m++;
                            }
                        cnt[i] = m;
                    }
                    if (cnt[i] < NSLOT) { sd[i][cnt[i]] = dp; sc[i][cnt[i]] = code; cnt[i]++; }
                    else ovf |= (1 << i);
                    if (dp < bv[i]) bv[i] = dp;
                }
                accf[i][j] = 0.0f;
            }
        }
    }

    // ---- merge per-token best across threads ----
    __syncthreads();
#pragma unroll
    for (int i = 0; i < 4; i++) atomicMin(&sbest[ty * 4 + i], fenc(bv[i]));
    __syncthreads();
#pragma unroll
    for (int i = 0; i < 4; i++) {
        int row = ty * 4 + i;
        if (ovf & (1 << i)) {
            atomicAdd(&scnt[row], 1000);
        } else {
            float gb = fdec(sbest[row]);
            for (int qq = 0; qq < cnt[i]; qq++)
                if (sd[i][qq] < gb + MARGIN) {
                    int pos = atomicAdd(&scnt[row], 1);
                    if (pos < 16) scand[row * 16 + pos] = sc[i][qq];
                }
        }
    }
    __syncthreads();

    // ---- exact fp32 re-rank: one token per thread ----
    if (tid < TOKT) {
        int row = tid;
        const float* ar = A32 + row * SA;
        float zn = 0.0f;
#pragma unroll 16
        for (int c4 = 0; c4 < 64; c4++) {
            float4 a = *(const float4*)(ar + c4 * 4);
            zn = fmaf(a.x, a.x, zn); zn = fmaf(a.y, a.y, zn);
            zn = fmaf(a.z, a.z, zn); zn = fmaf(a.w, a.w, zn);
        }
        int   c_n   = scnt[row];
        float bestx = 3.4e38f;
        int   besti = 0x7FFFFFFF;
        if (c_n <= 16) {
            for (int qq = 0; qq < c_n; qq++) {
                int code = scand[row * 16 + qq];
                const float4* er = (const float4*)(embed + (size_t)code * 256);
                float dot = 0.0f;
#pragma unroll 8
                for (int c4 = 0; c4 < 64; c4++) {
                    float4 e = __ldg(&er[c4]);
                    float4 a = *(const float4*)(ar + c4 * 4);
                    dot = fmaf(a.x, e.x, dot); dot = fmaf(a.y, e.y, dot);
                    dot = fmaf(a.z, e.z, dot); dot = fmaf(a.w, e.w, dot);
                }
                float v = (zn + EN[code]) - 2.0f * dot;
                if (v < bestx || (v == bestx && code < besti)) { bestx = v; besti = code; }
            }
        } else {   // overflow fallback: exact full scan (ascending -> first-min)
            for (int code = 0; code < NCODE; code++) {
                const float4* er = (const float4*)(embed + (size_t)code * 256);
                float dot = 0.0f;
                for (int c4 = 0; c4 < 64; c4++) {
                    float4 e = __ldg(&er[c4]);
                    float4 a = *(const float4*)(ar + c4 * 4);
                    dot = fmaf(a.x, e.x, dot); dot = fmaf(a.y, e.y, dot);
                    dot = fmaf(a.z, e.z, dot); dot = fmaf(a.w, e.w, dot);
                }
                float v = (zn + EN[code]) - 2.0f * dot;
                if (v < bestx) { bestx = v; besti = code; }
            }
        }
        g_idx[n0 + row] = besti;
    }
}

// ---------------- embed prep: transpose + half2 + |e|^2 + zero accum ----------------
__global__ void k_prep(const float* __restrict__ e) {
    int k = blockIdx.x;
    int t = threadIdx.x;                       // 64 threads, 4 dims each
    float4 v = ((const float4*)(e + (size_t)k * DIMC))[t];
    int c = t * 4;
    g_et[(c + 0) * NCODE + k] = v.x;
    g_et[(c + 1) * NCODE + k] = v.y;
    g_et[(c + 2) * NCODE + k] = v.z;
    g_et[(c + 3) * NCODE + k] = v.w;
    g_eh2[(2 * t + 0) * NCODE + k] = __floats2half2_rn(v.x, v.y);
    g_eh2[(2 * t + 1) * NCODE + k] = __floats2half2_rn(v.z, v.w);
    float s = v.x * v.x + v.y * v.y + v.z * v.z + v.w * v.w;
#pragma unroll
    for (int o = 16; o; o >>= 1) s += __shfl_down_sync(0xffffffffu, s, o);
    __shared__ float sh[2];
    if ((t & 31) == 0) sh[t >> 5] = s;
    __syncthreads();
    if (t == 0) {
        g_en[k]   = sh[0] + sh[1];
        g_hist[k] = 0;
        if (k == 0) g_loss = 0.0;
    }
}

// ---------------- z_q gather (vectorized) + loss ----------------
__global__ void k_epi(const float* __restrict__ z, float* __restrict__ out) {
    int i4  = blockIdx.x * 256 + threadIdx.x;      // over ZSZ/4
    int hw4 = i4 & 1023;
    int c   = (i4 >> 10) & 255;
    int b   = i4 >> 18;
    int4 kk = *(const int4*)(g_idx + (b << 12) + (hw4 << 2));
    float4 zv = ((const float4*)z)[i4];
    const float* row = g_et + c * NCODE;
    float dx = __ldg(&row[kk.x]) - zv.x;
    float dy = __ldg(&row[kk.y]) - zv.y;
    float dz = __ldg(&row[kk.z]) - zv.z;
    float dw = __ldg(&row[kk.w]) - zv.w;
    size_t o = OFF_ZQ + (size_t)i4 * 4;
    out[o + 0] = zv.x + dx;
    out[o + 1] = zv.y + dy;
    out[o + 2] = zv.z + dz;
    out[o + 3] = zv.w + dw;
    float s = dx * dx + dy * dy + dz * dz + dw * dw;
#pragma unroll
    for (int of = 16; of; of >>= 1) s += __shfl_down_sync(0xffffffffu, s, of);
    __shared__ float red[8];
    int t = threadIdx.x;
    if ((t & 31) == 0) red[t >> 5] = s;
    __syncthreads();
    if (t < 8) {
        float w = red[t];
#pragma unroll
        for (int of = 4; of; of >>= 1) w += __shfl_down_sync(0x000000ffu, w, of);
        if (t == 0) atomicAdd(&g_loss, (double)w);
    }
}

// ---------------- one-hot scatter + idx + histogram ----------------
__global__ void k_scat(float* __restrict__ out) {
    int n = blockIdx.x * 256 + threadIdx.x;
    int k = g_idx[n];
    out[OFF_MINENC + (size_t)n * NCODE + k] = 1.0f;
    out[OFF_IDX + n] = (float)k;
    atomicAdd(&g_hist[k], 1);
}

// ---------------- finalize ----------------
__global__ void k_fin(float* __restrict__ out) {
    int t = threadIdx.x;
    float em = (float)g_hist[t] * (1.0f / 65536.0f);
    float v = em * logf(em + 1e-10f);
    __shared__ float sh[32];
#pragma unroll
    for (int o = 16; o; o >>= 1) v += __shfl_down_sync(0xffffffffu, v, o);
    if ((t & 31) == 0) sh[t >> 5] = v;
    __syncthreads();
    if (t < 32) {
        float w = sh[t];
#pragma unroll
        for (int o = 16; o; o >>= 1) w += __shfl_down_sync(0xffffffffu, w, o);
        if (t == 0) {
            out[OFF_PERP] = expf(-w);
            out[0] = (float)(g_loss * (1.25 / 16777216.0));
        }
    }
}

// ---------------- launch ----------------
extern "C" void kernel_launch(void* const* d_in, const int* in_sizes, int n_in,
                              void* d_out, int out_size) {
    const float* z = (const float*)d_in[0];
    const float* e = (const float*)d_in[1];
    float* out = (float*)d_out;
    (void)in_sizes; (void)n_in; (void)out_size;

    static int attr_set = 0;
    if (!attr_set) {
        cudaFuncSetAttribute(k_pass1, cudaFuncAttributeMaxDynamicSharedMemorySize, SMEM_BYTES);
        attr_set = 1;
    }

    k_prep  <<<NCODE, 64>>>(e);
    k_pass1 <<<NTOK / TOKT, 256, SMEM_BYTES>>>(z, e);
    cudaMemsetAsync(out + OFF_MINENC, 0, 268435456ULL);
    k_epi   <<<ZSZ / 1024, 256>>>(z, out);
    k_scat  <<<NTOK / 256, 256>>>(out);
    k_fin   <<<1, 1024>>>(out);
}